// round 16
// baseline (speedup 1.0000x reference)
#include <cuda_runtime.h>
#include <cuda_bf16.h>

#define B_    32
#define T_    512
#define N_    128
#define BN_   4096
#define K_    4
#define PMAX_ 64
#define MINP_ 16
#define CMAX_ 32   // T/MINP

#define GATHERED_ELEMS 33554432ull   // 32*128*4*32*64
#define KAMP_OFFSET    67108864ull   // 2 * GATHERED_ELEMS

#define SSTRIDE 520                  // padded length of each shifted copy (16B-aligned)

// ---------------------------------------------------------------------------
// Fused persistent kernel: one block (256 threads) handles TWO pair-units
// (4 sequences) sequentially. Unit-2's FFT phase overlaps unit-1's streaming
// store drain (stores are fire-and-forget); grid 1024 = single wave.
// Per unit: DIF radix-4 FFT (natural-order input, register sub-FFTs via
// shfl), top-k in bit-reversed storage, gather via SHIFTED smem copies
// (any unaligned 4-float window = one aligned conflict-free LDS.128),
// all output stores STG.128 streaming. Twiddles inline via sincospif.
// ---------------------------------------------------------------------------
__global__ __launch_bounds__(256, 8) void pt_fused(const float* __restrict__ x,
                                                   float* __restrict__ out) {
    __shared__ float sh[2][4][SSTRIDE];         // shifted copies: sh[s][a][i]=seq_s[i+a]
    __shared__ float re[1024], im[1024];        // FFT workspace; re becomes amp
    __shared__ int   sP[2][4], sCyc[2][4], sBase[2][4];

    const int tid  = threadIdx.x;
    const int lane = tid & 31;
    const int wid  = tid >> 5;
    const int ffti = tid >> 7;          // which FFT this thread works on
    const int base = ffti << 9;
    const int tl   = tid & 127;

#pragma unroll 1
    for (int u = 0; u < 2; u++) {
        const int bn0 = (blockIdx.x * 2 + u) * 2;

        // loop-top barrier: prior unit's gather reads of sh must complete
        // before this unit's load overwrites it (no-op cost on u==0)
        __syncthreads();

        // ---- load both sequences; write 4 shifted copies (conflict-free STS) ----
        {
            const int b  = bn0 >> 7;
            const int n0 = bn0 & 127;
            const float2* xp = (const float2*)(x + (size_t)b * T_ * N_ + n0);
            float2 v0 = xp[(size_t)tid * (N_ / 2)];
            float2 v1 = xp[(size_t)(tid + 256) * (N_ / 2)];
            int t1 = tid + 256;
#pragma unroll
            for (int a = 0; a < 4; a++) {
                if (tid >= a) { sh[0][a][tid - a] = v0.x; sh[1][a][tid - a] = v0.y; }
                sh[0][a][t1 - a] = v1.x; sh[1][a][t1 - a] = v1.y;
            }
        }
        __syncthreads();

        // ---- DIF stages 1+2 (radix-4, q=128), real input, lanes contiguous ----
        {
            const float* sq0 = sh[ffti][0];
            int i = tl;
            float a0 = sq0[i];
            float a1 = sq0[i + 128];
            float a2 = sq0[i + 256];
            float a3 = sq0[i + 384];
            float w1r, w1i, w3r, w3i;
            sincospif(-(float)i / 256.f, &w1i, &w1r);          // W^i
            sincospif(-(float)i / 128.f, &w3i, &w3r);          // W^{2i}
            // W^{i+128} = W^i * (-i):
            float w2r = w1i, w2i = -w1r;
            float y0 = a0 + a2, y1 = a1 + a3;
            float d02 = a0 - a2, d13 = a1 - a3;
            float y2r = d02 * w1r, y2i = d02 * w1i;
            float y3r = d13 * w2r, y3i = d13 * w2i;
            re[base + i]       = y0 + y1;          im[base + i]       = 0.0f;
            float d01 = y0 - y1;
            re[base + i + 128] = d01 * w3r;        im[base + i + 128] = d01 * w3i;
            re[base + i + 256] = y2r + y3r;        im[base + i + 256] = y2i + y3i;
            float dr = y2r - y3r, di = y2i - y3i;
            re[base + i + 384] = dr * w3r - di * w3i;
            im[base + i + 384] = dr * w3i + di * w3r;
        }
        __syncthreads();

        // ---- DIF stages 3+4 (radix-4, q=32), lanes contiguous in k ----
        {
            int grp = tl >> 5, k = tl & 31;
            int i0 = base + (grp << 7) + k;
            float x0r = re[i0],      x0i = im[i0];
            float x1r = re[i0 + 32], x1i = im[i0 + 32];
            float x2r = re[i0 + 64], x2i = im[i0 + 64];
            float x3r = re[i0 + 96], x3i = im[i0 + 96];
            float war, wai, wcr, wci;
            sincospif(-(float)k / 64.f, &wai, &war);           // W^{4k}
            sincospif(-(float)k / 32.f, &wci, &wcr);           // W^{8k}
            // W^{4k+128} = W^{4k} * (-i):
            float wbr = wai, wbi = -war;
            float y0r = x0r + x2r, y0i = x0i + x2i;
            float y1r = x1r + x3r, y1i = x1i + x3i;
            float dar = x0r - x2r, dai = x0i - x2i;
            float dbr = x1r - x3r, dbi = x1i - x3i;
            float y2r = dar * war - dai * wai, y2i = dar * wai + dai * war;
            float y3r = dbr * wbr - dbi * wbi, y3i = dbr * wbi + dbi * wbr;
            re[i0]      = y0r + y1r;  im[i0]      = y0i + y1i;
            float d0r = y0r - y1r, d0i = y0i - y1i;
            re[i0 + 32] = d0r * wcr - d0i * wci;  im[i0 + 32] = d0r * wci + d0i * wcr;
            re[i0 + 64] = y2r + y3r;  im[i0 + 64] = y2i + y3i;
            float d2r = y2r - y3r, d2i = y2i - y3i;
            re[i0 + 96] = d2r * wcr - d2i * wci;  im[i0 + 96] = d2r * wci + d2i * wcr;
        }
        __syncthreads();

        // ---- 32-pt sub-FFTs in registers: warp w owns chunks 4w..4w+3 ----
        {
            float w16r, w16i, w8r, w8i, w4r, w4i;
            sincospif(-(float)(lane & 15) / 16.f, &w16i, &w16r);  // W^{16j}
            sincospif(-(float)(lane & 7)  /  8.f, &w8i,  &w8r);   // W^{32j}
            sincospif(-(float)(lane & 3)  /  4.f, &w4i,  &w4r);   // W^{64j}
#pragma unroll
            for (int q = 0; q < 4; q++) {
                int cb = ((wid << 2) + q) << 5;        // chunk base in storage
                float ar = re[cb + lane], ai = im[cb + lane];
                {
                    float pr = __shfl_xor_sync(0xffffffffu, ar, 16);
                    float pi = __shfl_xor_sync(0xffffffffu, ai, 16);
                    bool up = lane & 16;
                    float dr = pr - ar, di = pi - ai;
                    float sr = ar + pr, si = ai + pi;
                    ar = up ? (dr * w16r - di * w16i) : sr;
                    ai = up ? (dr * w16i + di * w16r) : si;
                }
                {
                    float pr = __shfl_xor_sync(0xffffffffu, ar, 8);
                    float pi = __shfl_xor_sync(0xffffffffu, ai, 8);
                    bool up = lane & 8;
                    float dr = pr - ar, di = pi - ai;
                    float sr = ar + pr, si = ai + pi;
                    ar = up ? (dr * w8r - di * w8i) : sr;
                    ai = up ? (dr * w8i + di * w8r) : si;
                }
                {
                    float pr = __shfl_xor_sync(0xffffffffu, ar, 4);
                    float pi = __shfl_xor_sync(0xffffffffu, ai, 4);
                    bool up = lane & 4;
                    float dr = pr - ar, di = pi - ai;
                    float sr = ar + pr, si = ai + pi;
                    ar = up ? (dr * w4r - di * w4i) : sr;
                    ai = up ? (dr * w4i + di * w4r) : si;
                }
                {
                    float pr = __shfl_xor_sync(0xffffffffu, ar, 2);
                    float pi = __shfl_xor_sync(0xffffffffu, ai, 2);
                    bool up = lane & 2;
                    bool j1 = lane & 1;
                    float dr = pr - ar, di = pi - ai;
                    float sr = ar + pr, si = ai + pi;
                    float rr = j1 ? di : dr;
                    float ri = j1 ? -dr : di;
                    ar = up ? rr : sr;
                    ai = up ? ri : si;
                }
                {
                    float pr = __shfl_xor_sync(0xffffffffu, ar, 1);
                    float pi = __shfl_xor_sync(0xffffffffu, ai, 1);
                    bool up = lane & 1;
                    ar = up ? (pr - ar) : (ar + pr);
                    ai = up ? (pi - ai) : (ai + pi);
                }
                re[cb + lane] = sqrtf(ar * ar + ai * ai);   // amp into re
            }
        }
        __syncthreads();

        // ---- top-4: warp 0 -> seq A, warp 1 -> seq B (smem re-scan) ----
        // Storage slot p holds frequency brev9(p). Candidates = bins 1..256:
        // t=0 -> p=1 (freq 256); t>=1 -> p=2t (freqs 1..255). Tie-break: lower freq.
        if (wid < 2) {
            const int fbase = wid << 9;
#pragma unroll
            for (int pass = 0; pass < K_; pass++) {
                float bv = -1.0f; int bf = 0x7fffffff;
#pragma unroll
                for (int j = 0; j < 8; j++) {
                    int t = lane + 32 * j;
                    int p = (t == 0) ? 1 : (2 * t);
                    float vv = re[fbase + p];
                    int   f  = (int)(__brev((unsigned)p) >> 23);
                    if (vv > bv || (vv == bv && f < bf)) { bv = vv; bf = f; }
                }
#pragma unroll
                for (int off = 16; off > 0; off >>= 1) {
                    float ov = __shfl_down_sync(0xffffffffu, bv, off);
                    int   of = __shfl_down_sync(0xffffffffu, bf, off);
                    if (ov > bv || (ov == bv && of < bf)) { bv = ov; bf = of; }
                }
                if (lane == 0) {
                    out[KAMP_OFFSET + (size_t)(bn0 + wid) * K_ + pass] = bv;
                    re[fbase + (int)(__brev((unsigned)bf) >> 23)] = -2.0f; // exclude
                    int P = T_ / bf;                       // bf = frequency >= 1
                    P = P < MINP_ ? MINP_ : (P > PMAX_ ? PMAX_ : P);
                    int cyc = T_ / P;
                    sP[wid][pass] = P; sCyc[wid][pass] = cyc;
                    sBase[wid][pass] = T_ - cyc * P;
                }
                __syncwarp();
            }
        }
        __syncthreads();

        // ---- gather + mask: one LDS.128 + two STG.128 per float4 chunk ----
        // Window seq[off..off+3] (any alignment) = aligned float4 of copy a=off&3.
        // Masked components select 0 (FSEL: no NaN leak from garbage smem).
        {
            float4* gb = (float4*)(out + (size_t)(bn0 * K_) * (CMAX_ * PMAX_)) + tid;
            float4* mb = (float4*)(out + GATHERED_ELEMS +
                                   (size_t)(bn0 * K_) * (CMAX_ * PMAX_)) + tid;
#pragma unroll
            for (int sidx = 0; sidx < 2; sidx++) {
#pragma unroll
                for (int k = 0; k < K_; k++) {
                    const int P = sP[sidx][k], cyc = sCyc[sidx][k], bas = sBase[sidx][k];
#pragma unroll
                    for (int i = 0; i < 2; i++) {
                        int e4 = tid + 256 * i;          // float4 index 0..511
                        int c  = e4 >> 4;                // cycle row
                        int p  = (e4 & 15) << 2;         // position in period
                        int off = bas + c * P + p;
                        int idx4 = min(off >> 2, (SSTRIDE - 4) >> 2);
                        float4 v = *((const float4*)sh[sidx][off & 3] + idx4);
                        bool crow = (c < cyc);
                        bool b0 = crow && (p     < P);
                        bool b1 = crow && (p + 1 < P);
                        bool b2 = crow && (p + 2 < P);
                        bool b3 = crow && (p + 3 < P);
                        float4 g = make_float4(b0 ? v.x : 0.0f, b1 ? v.y : 0.0f,
                                               b2 ? v.z : 0.0f, b3 ? v.w : 0.0f);
                        float4 m = make_float4(b0 ? 1.0f : 0.0f, b1 ? 1.0f : 0.0f,
                                               b2 ? 1.0f : 0.0f, b3 ? 1.0f : 0.0f);
                        __stcs(gb + 256 * i, g);
                        __stcs(mb + 256 * i, m);
                    }
                    gb += 512;  mb += 512;               // next 8KB tile
                }
            }
        }
    }
}

// ---------------------------------------------------------------------------
extern "C" void kernel_launch(void* const* d_in, const int* in_sizes, int n_in,
                              void* d_out, int out_size) {
    const float* x = (const float*)d_in[0];
    float* out = (float*)d_out;

    pt_fused<<<BN_ / 4, 256>>>(x, out);
}

// round 17
// speedup vs baseline: 1.1234x; 1.1234x over previous
#include <cuda_runtime.h>
#include <cuda_bf16.h>

#define B_    32
#define T_    512
#define N_    128
#define BN_   4096
#define K_    4
#define PMAX_ 64
#define MINP_ 16
#define CMAX_ 32   // T/MINP

#define GATHERED_ELEMS 33554432ull   // 32*128*4*32*64
#define KAMP_OFFSET    67108864ull   // 2 * GATHERED_ELEMS

#define SSTRIDE 520                  // padded length of each shifted copy (16B-aligned)

// ---------------------------------------------------------------------------
// Fused kernel: one block (256 threads) per PAIR of sequences.
// DIF radix-4 FFT (natural-order input, register sub-FFTs via shfl), top-k in
// bit-reversed storage, then gather via SHIFTED smem copies: any unaligned
// 4-float window is one aligned conflict-free LDS.128; all stores STG.128.
// Twiddles computed inline via sincospif (no init kernel, no table loads).
// Output uses plain write-back stores: full-line writes (no RFO) leave dirty
// L2 at kernel end, which drains during the next graph replay's FFT phase.
// ---------------------------------------------------------------------------
__global__ __launch_bounds__(256, 8) void pt_fused(const float* __restrict__ x,
                                                   float* __restrict__ out) {
    __shared__ float sh[2][4][SSTRIDE];         // shifted copies: sh[s][a][i]=seq_s[i+a]
    __shared__ float re[1024], im[1024];        // FFT workspace; re becomes amp
    __shared__ int   sP[2][4], sCyc[2][4], sBase[2][4];

    const int bn0  = blockIdx.x * 2;
    const int tid  = threadIdx.x;
    const int lane = tid & 31;
    const int wid  = tid >> 5;

    // ---- load both sequences; write 4 shifted copies each (conflict-free STS) ----
    {
        const int b  = bn0 >> 7;
        const int n0 = bn0 & 127;
        const float2* xp = (const float2*)(x + (size_t)b * T_ * N_ + n0);
        float2 v0 = xp[(size_t)tid * (N_ / 2)];
        float2 v1 = xp[(size_t)(tid + 256) * (N_ / 2)];
        int t1 = tid + 256;
#pragma unroll
        for (int a = 0; a < 4; a++) {
            if (tid >= a) { sh[0][a][tid - a] = v0.x; sh[1][a][tid - a] = v0.y; }
            sh[0][a][t1 - a] = v1.x; sh[1][a][t1 - a] = v1.y;
        }
    }
    __syncthreads();

    const int ffti = tid >> 7;          // which FFT this thread works on
    const int base = ffti << 9;
    const int tl   = tid & 127;

    // ---- DIF stages 1+2 (radix-4, q=128), real input, lanes contiguous ----
    {
        const float* sq0 = sh[ffti][0];
        int i = tl;
        float a0 = sq0[i];
        float a1 = sq0[i + 128];
        float a2 = sq0[i + 256];
        float a3 = sq0[i + 384];
        float w1r, w1i, w3r, w3i;
        sincospif(-(float)i / 256.f, &w1i, &w1r);          // W^i
        sincospif(-(float)i / 128.f, &w3i, &w3r);          // W^{2i}
        // W^{i+128} = W^i * (-i):
        float w2r = w1i, w2i = -w1r;
        float y0 = a0 + a2, y1 = a1 + a3;
        float d02 = a0 - a2, d13 = a1 - a3;
        float y2r = d02 * w1r, y2i = d02 * w1i;
        float y3r = d13 * w2r, y3i = d13 * w2i;
        re[base + i]       = y0 + y1;          im[base + i]       = 0.0f;
        float d01 = y0 - y1;
        re[base + i + 128] = d01 * w3r;        im[base + i + 128] = d01 * w3i;
        re[base + i + 256] = y2r + y3r;        im[base + i + 256] = y2i + y3i;
        float dr = y2r - y3r, di = y2i - y3i;
        re[base + i + 384] = dr * w3r - di * w3i;
        im[base + i + 384] = dr * w3i + di * w3r;
    }
    __syncthreads();

    // ---- DIF stages 3+4 (radix-4, q=32), lanes contiguous in k ----
    {
        int grp = tl >> 5, k = tl & 31;
        int i0 = base + (grp << 7) + k;
        float x0r = re[i0],      x0i = im[i0];
        float x1r = re[i0 + 32], x1i = im[i0 + 32];
        float x2r = re[i0 + 64], x2i = im[i0 + 64];
        float x3r = re[i0 + 96], x3i = im[i0 + 96];
        float war, wai, wcr, wci;
        sincospif(-(float)k / 64.f, &wai, &war);           // W^{4k}
        sincospif(-(float)k / 32.f, &wci, &wcr);           // W^{8k}
        // W^{4k+128} = W^{4k} * (-i):
        float wbr = wai, wbi = -war;
        float y0r = x0r + x2r, y0i = x0i + x2i;
        float y1r = x1r + x3r, y1i = x1i + x3i;
        float dar = x0r - x2r, dai = x0i - x2i;
        float dbr = x1r - x3r, dbi = x1i - x3i;
        float y2r = dar * war - dai * wai, y2i = dar * wai + dai * war;
        float y3r = dbr * wbr - dbi * wbi, y3i = dbr * wbi + dbi * wbr;
        re[i0]      = y0r + y1r;  im[i0]      = y0i + y1i;
        float d0r = y0r - y1r, d0i = y0i - y1i;
        re[i0 + 32] = d0r * wcr - d0i * wci;  im[i0 + 32] = d0r * wci + d0i * wcr;
        re[i0 + 64] = y2r + y3r;  im[i0 + 64] = y2i + y3i;
        float d2r = y2r - y3r, d2i = y2i - y3i;
        re[i0 + 96] = d2r * wcr - d2i * wci;  im[i0 + 96] = d2r * wci + d2i * wcr;
    }
    __syncthreads();

    // ---- 32-pt sub-FFTs in registers: warp w owns chunks 4w..4w+3 ----
    {
        float w16r, w16i, w8r, w8i, w4r, w4i;
        sincospif(-(float)(lane & 15) / 16.f, &w16i, &w16r);  // W^{16j}
        sincospif(-(float)(lane & 7)  /  8.f, &w8i,  &w8r);   // W^{32j}
        sincospif(-(float)(lane & 3)  /  4.f, &w4i,  &w4r);   // W^{64j}
#pragma unroll
        for (int q = 0; q < 4; q++) {
            int cb = ((wid << 2) + q) << 5;        // chunk base in storage
            float ar = re[cb + lane], ai = im[cb + lane];
            {
                float pr = __shfl_xor_sync(0xffffffffu, ar, 16);
                float pi = __shfl_xor_sync(0xffffffffu, ai, 16);
                bool up = lane & 16;
                float dr = pr - ar, di = pi - ai;
                float sr = ar + pr, si = ai + pi;
                ar = up ? (dr * w16r - di * w16i) : sr;
                ai = up ? (dr * w16i + di * w16r) : si;
            }
            {
                float pr = __shfl_xor_sync(0xffffffffu, ar, 8);
                float pi = __shfl_xor_sync(0xffffffffu, ai, 8);
                bool up = lane & 8;
                float dr = pr - ar, di = pi - ai;
                float sr = ar + pr, si = ai + pi;
                ar = up ? (dr * w8r - di * w8i) : sr;
                ai = up ? (dr * w8i + di * w8r) : si;
            }
            {
                float pr = __shfl_xor_sync(0xffffffffu, ar, 4);
                float pi = __shfl_xor_sync(0xffffffffu, ai, 4);
                bool up = lane & 4;
                float dr = pr - ar, di = pi - ai;
                float sr = ar + pr, si = ai + pi;
                ar = up ? (dr * w4r - di * w4i) : sr;
                ai = up ? (dr * w4i + di * w4r) : si;
            }
            {
                float pr = __shfl_xor_sync(0xffffffffu, ar, 2);
                float pi = __shfl_xor_sync(0xffffffffu, ai, 2);
                bool up = lane & 2;
                bool j1 = lane & 1;
                float dr = pr - ar, di = pi - ai;
                float sr = ar + pr, si = ai + pi;
                float rr = j1 ? di : dr;
                float ri = j1 ? -dr : di;
                ar = up ? rr : sr;
                ai = up ? ri : si;
            }
            {
                float pr = __shfl_xor_sync(0xffffffffu, ar, 1);
                float pi = __shfl_xor_sync(0xffffffffu, ai, 1);
                bool up = lane & 1;
                ar = up ? (pr - ar) : (ar + pr);
                ai = up ? (pi - ai) : (ai + pi);
            }
            re[cb + lane] = sqrtf(ar * ar + ai * ai);   // amp into re
        }
    }
    __syncthreads();

    // ---- top-4: warp 0 -> seq A, warp 1 -> seq B (smem re-scan) ----
    // Storage slot p holds frequency brev9(p). Candidates = bins 1..256:
    // t=0 -> p=1 (freq 256); t>=1 -> p=2t (freqs 1..255). Tie-break: lower freq.
    if (wid < 2) {
        const int fbase = wid << 9;
#pragma unroll
        for (int pass = 0; pass < K_; pass++) {
            float bv = -1.0f; int bf = 0x7fffffff;
#pragma unroll
            for (int j = 0; j < 8; j++) {
                int t = lane + 32 * j;
                int p = (t == 0) ? 1 : (2 * t);
                float vv = re[fbase + p];
                int   f  = (int)(__brev((unsigned)p) >> 23);
                if (vv > bv || (vv == bv && f < bf)) { bv = vv; bf = f; }
            }
#pragma unroll
            for (int off = 16; off > 0; off >>= 1) {
                float ov = __shfl_down_sync(0xffffffffu, bv, off);
                int   of = __shfl_down_sync(0xffffffffu, bf, off);
                if (ov > bv || (ov == bv && of < bf)) { bv = ov; bf = of; }
            }
            if (lane == 0) {
                out[KAMP_OFFSET + (size_t)(bn0 + wid) * K_ + pass] = bv;
                re[fbase + (int)(__brev((unsigned)bf) >> 23)] = -2.0f; // exclude
                int P = T_ / bf;                       // bf = frequency >= 1
                P = P < MINP_ ? MINP_ : (P > PMAX_ ? PMAX_ : P);
                int cyc = T_ / P;
                sP[wid][pass] = P; sCyc[wid][pass] = cyc;
                sBase[wid][pass] = T_ - cyc * P;
            }
            __syncwarp();
        }
    }
    __syncthreads();

    // ---- gather + mask: one LDS.128 + two STG.128 per float4 chunk ----
    // Window seq[off..off+3] (any alignment) = aligned float4 of copy a=off&3.
    // Masked components select 0 (FSEL: no NaN leak from garbage smem).
    // Plain write-back stores (full-line, no RFO): dirty L2 at kernel end
    // drains during the next replay's compute phase.
    {
        float4* gb = (float4*)(out + (size_t)(bn0 * K_) * (CMAX_ * PMAX_)) + tid;
        float4* mb = (float4*)(out + GATHERED_ELEMS +
                               (size_t)(bn0 * K_) * (CMAX_ * PMAX_)) + tid;
#pragma unroll
        for (int sidx = 0; sidx < 2; sidx++) {
#pragma unroll
            for (int k = 0; k < K_; k++) {
                const int P = sP[sidx][k], cyc = sCyc[sidx][k], bas = sBase[sidx][k];
#pragma unroll
                for (int i = 0; i < 2; i++) {
                    int e4 = tid + 256 * i;          // float4 index 0..511
                    int c  = e4 >> 4;                // cycle row
                    int p  = (e4 & 15) << 2;         // position in period
                    int off = bas + c * P + p;
                    int idx4 = min(off >> 2, (SSTRIDE - 4) >> 2);
                    float4 v = *((const float4*)sh[sidx][off & 3] + idx4);
                    bool crow = (c < cyc);
                    bool b0 = crow && (p     < P);
                    bool b1 = crow && (p + 1 < P);
                    bool b2 = crow && (p + 2 < P);
                    bool b3 = crow && (p + 3 < P);
                    float4 g = make_float4(b0 ? v.x : 0.0f, b1 ? v.y : 0.0f,
                                           b2 ? v.z : 0.0f, b3 ? v.w : 0.0f);
                    float4 m = make_float4(b0 ? 1.0f : 0.0f, b1 ? 1.0f : 0.0f,
                                           b2 ? 1.0f : 0.0f, b3 ? 1.0f : 0.0f);
                    gb[256 * i] = g;
                    mb[256 * i] = m;
                }
                gb += 512;  mb += 512;               // next 8KB tile
            }
        }
    }
}

// ---------------------------------------------------------------------------
extern "C" void kernel_launch(void* const* d_in, const int* in_sizes, int n_in,
                              void* d_out, int out_size) {
    const float* x = (const float*)d_in[0];
    float* out = (float*)d_out;

    pt_fused<<<BN_ / 2, 256>>>(x, out);
}